// round 1
// baseline (speedup 1.0000x reference)
#include <cuda_runtime.h>
#include <cuda_bf16.h>
#include <cstdint>

#define DN 256          // number of nodes (D)
#define HN 64           // hidden width (H)
#define BN 8192         // batch
#define ROWS 64         // rows per block
#define THREADS 256
#define NBLOCKS (BN / ROWS)   // 128

// Masked, transposed weights: Wt[i][j][k] = W1[i,k,j] * sigmoid(adj_logits[j,i]) * (j != i)
__device__ float g_Wt[DN * DN * HN];   // 16.8 MB scratch (allowed: __device__ global)

// ---------------- packed f32x2 helpers (sm_103a) ----------------
__device__ __forceinline__ unsigned long long pack2(float lo, float hi) {
    unsigned long long r;
    asm("mov.b64 %0, {%1, %2};" : "=l"(r) : "f"(lo), "f"(hi));
    return r;
}
__device__ __forceinline__ void unpack2(unsigned long long v, float& lo, float& hi) {
    asm("mov.b64 {%0, %1}, %2;" : "=f"(lo), "=f"(hi) : "l"(v));
}
__device__ __forceinline__ unsigned long long fma2(unsigned long long a,
                                                   unsigned long long b,
                                                   unsigned long long c) {
    unsigned long long d;
    asm("fma.rn.f32x2 %0, %1, %2, %3;" : "=l"(d) : "l"(a), "l"(b), "l"(c));
    return d;
}

__device__ __forceinline__ void cp_async16(void* smem_dst, const void* gsrc) {
    uint32_t s = (uint32_t)__cvta_generic_to_shared(smem_dst);
    asm volatile("cp.async.cg.shared.global [%0], [%1], 16;" :: "r"(s), "l"(gsrc));
}
__device__ __forceinline__ void cp_commit() {
    asm volatile("cp.async.commit_group;");
}
__device__ __forceinline__ void cp_wait_all() {
    asm volatile("cp.async.wait_group 0;" ::: "memory");
}

// ---------------- precompute: fold adjacency sigmoid into transposed weights ----------------
__global__ void precompute_kernel(const float* __restrict__ W1,
                                  const float* __restrict__ adj_logits) {
    int i = blockIdx.x;
    __shared__ float tile[64][65];
    __shared__ float asig[64];
    const float* W1i = W1 + (size_t)i * HN * DN;   // [H][D], j fastest
    float* Wti = g_Wt + (size_t)i * DN * HN;       // [D][H], k fastest

    for (int j0 = 0; j0 < DN; j0 += 64) {
        for (int idx = threadIdx.x; idx < 64 * 64; idx += blockDim.x) {
            int k = idx >> 6, jj = idx & 63;
            tile[k][jj] = W1i[k * DN + j0 + jj];          // coalesced read
        }
        if (threadIdx.x < 64) {
            int j = j0 + threadIdx.x;
            float l = adj_logits[j * DN + i];
            float s = 1.0f / (1.0f + __expf(-l));
            asig[threadIdx.x] = (j == i) ? 0.0f : s;
        }
        __syncthreads();
        for (int idx = threadIdx.x; idx < 64 * 64; idx += blockDim.x) {
            int jj = idx >> 6, k = idx & 63;
            Wti[(j0 + jj) * HN + k] = tile[k][jj] * asig[jj];  // coalesced write
        }
        __syncthreads();
    }
}

// ---------------- main sequential-per-row kernel ----------------
// smem layout: z_s[DN][ROWS] (64 KB) | W buffers 2 x [DN][HN] (2 x 64 KB)
extern __shared__ float smem_dyn[];

__global__ void __launch_bounds__(THREADS, 1)
scm_kernel(const float* __restrict__ noise,
           const float* __restrict__ b1,
           const float* __restrict__ W2,
           const float* __restrict__ b2,
           const float* __restrict__ log_sigma,
           float* __restrict__ out) {
    float* z_s = smem_dyn;                   // [DN][ROWS], j-major, row minor
    float* W_b = smem_dyn + DN * ROWS;       // two buffers of [DN][HN]

    const int tid  = threadIdx.x;
    const int lane = tid & 31;
    const int wid  = tid >> 5;
    const int row0 = blockIdx.x * ROWS;
    const int rb   = wid * 8;                // 8 rows per warp
    const int k0   = lane;
    const int k1   = lane + 32;

    // zero z (columns >= i are read as zero in the rounded-up K loop)
    for (int idx = tid; idx < DN * ROWS; idx += THREADS) z_s[idx] = 0.0f;

    // prefetch W for node 1 into buffer 1 (node 0 has jmax = 0, needs no weights)
    {
        const int jmax1 = 4;  // (1+3)&~3
        const float4* src = (const float4*)(g_Wt + (size_t)1 * DN * HN);
        float4* dst = (float4*)(W_b + 1 * DN * HN);
        for (int idx = tid; idx < jmax1 * (HN / 4); idx += THREADS)
            cp_async16(dst + idx, src + idx);
        cp_commit();
    }
    __syncthreads();

    for (int i = 0; i < DN; ++i) {
        cp_wait_all();
        __syncthreads();   // W[i] ready in buffer (i&1); z column i-1 visible

        // prefetch W for node i+1 into the other buffer (overlaps compute)
        if (i + 1 < DN) {
            int jn = (i + 4) & ~3; if (jn > DN) jn = DN;
            const float4* src = (const float4*)(g_Wt + (size_t)(i + 1) * DN * HN);
            float4* dst = (float4*)(W_b + ((i + 1) & 1) * DN * HN);
            for (int idx = tid; idx < jn * (HN / 4); idx += THREADS)
                cp_async16(dst + idx, src + idx);
        }
        cp_commit();

        int jmax = (i + 3) & ~3; if (jmax > DN) jmax = DN;
        const float* W_s = W_b + (i & 1) * DN * HN;

        // per-lane node params
        float b10 = b1[i * HN + k0], b11 = b1[i * HN + k1];
        float w20 = W2[i * HN + k0], w21 = W2[i * HN + k1];

        // accumulate: acc[p][c] = packed rows (rb+2p, rb+2p+1) for k = lane + 32*c
        unsigned long long acc[4][2];
        #pragma unroll
        for (int p = 0; p < 4; ++p) { acc[p][0] = 0ull; acc[p][1] = 0ull; }

        #pragma unroll 4
        for (int j = 0; j < jmax; ++j) {
            float w0 = W_s[j * HN + k0];
            float w1 = W_s[j * HN + k1];
            unsigned long long bw0 = pack2(w0, w0);
            unsigned long long bw1 = pack2(w1, w1);
            const float* zrow = &z_s[j * ROWS + rb];
            #pragma unroll
            for (int p = 0; p < 4; ++p) {
                unsigned long long z2 =
                    *reinterpret_cast<const unsigned long long*>(zrow + 2 * p);
                acc[p][0] = fma2(z2, bw0, acc[p][0]);
                acc[p][1] = fma2(z2, bw1, acc[p][1]);
            }
        }

        // epilogue: h = silu(acc + b1), partial = h . w2, reduce over 64 k
        float red[8];
        #pragma unroll
        for (int p = 0; p < 4; ++p) {
            float a0l, a0h, a1l, a1h;
            unpack2(acc[p][0], a0l, a0h);
            unpack2(acc[p][1], a1l, a1h);
            float x, h;
            x = a0l + b10; h = __fdividef(x, 1.0f + __expf(-x)); red[2*p]     = h * w20;
            x = a1l + b11; h = __fdividef(x, 1.0f + __expf(-x)); red[2*p]    += h * w21;
            x = a0h + b10; h = __fdividef(x, 1.0f + __expf(-x)); red[2*p + 1] = h * w20;
            x = a1h + b11; h = __fdividef(x, 1.0f + __expf(-x)); red[2*p + 1] += h * w21;
        }
        #pragma unroll
        for (int p = 0; p < 8; ++p) {
            #pragma unroll
            for (int off = 16; off; off >>= 1)
                red[p] += __shfl_xor_sync(0xffffffffu, red[p], off);
        }

        if (lane == 0) {
            float b2i = b2[i];
            float sig = __expf(log_sigma[i]);
            #pragma unroll
            for (int r = 0; r < 8; ++r) {
                float val = red[r] + b2i +
                            sig * noise[(size_t)(row0 + rb + r) * DN + i];
                z_s[i * ROWS + rb + r] = val;
            }
        }
        __syncthreads();   // z column i visible; W buffer readers done before overwrite
    }

    // write out z: global-coalesced (smem bank conflicts here are negligible)
    for (int idx = tid; idx < ROWS * DN; idx += THREADS) {
        int r = idx >> 8;        // 0..63
        int j = idx & 255;       // 0..255
        out[(size_t)(row0 + r) * DN + j] = z_s[j * ROWS + r];
    }
}

extern "C" void kernel_launch(void* const* d_in, const int* in_sizes, int n_in,
                              void* d_out, int out_size) {
    const float* noise      = (const float*)d_in[0];
    const float* adj_logits = (const float*)d_in[1];
    const float* W1         = (const float*)d_in[2];
    const float* b1         = (const float*)d_in[3];
    const float* W2         = (const float*)d_in[4];
    const float* b2         = (const float*)d_in[5];
    const float* log_sigma  = (const float*)d_in[6];
    float* out = (float*)d_out;

    precompute_kernel<<<DN, 256>>>(W1, adj_logits);

    size_t smem_bytes = (size_t)(DN * ROWS + 2 * DN * HN) * sizeof(float);  // 192 KB
    cudaFuncSetAttribute(scm_kernel, cudaFuncAttributeMaxDynamicSharedMemorySize,
                         (int)smem_bytes);
    scm_kernel<<<NBLOCKS, THREADS, smem_bytes>>>(noise, b1, W2, b2, log_sigma, out);
}